// round 6
// baseline (speedup 1.0000x reference)
#include <cuda_runtime.h>
#include <cuda_fp16.h>

// Problem constants (fixed by the dataset)
#define Nn 50000
#define Ee 800000
#define Ff 128
#define Hh 256
#define Gg 512
#define Tt 5

#define NBLK 196   // ceil(Nn/256) scan blocks

// W16 offsets (halves): W0t 256x128, W1..3t 256x256
#define W0OFF 0
#define W1OFF 32768
#define W2OFF 98304
#define W3OFF 163840

// ---------------- scratch (device globals; no allocations allowed) ----------
__device__ int    g_cnt[Nn];
__device__ int    g_rowptr[Nn + 1];
__device__ int    g_cursor[Nn];
__device__ int    g_col[Ee];
__device__ float  g_dinv[Nn];
__device__ int    g_bsum[NBLK];
__device__ int    g_boff[NBLK];
__device__ __half g_W16[229376];             // transposed fp16 weights [n][k]
__device__ __half g_bufA[(size_t)Nn * Hh];   // ping (features, fp16)
__device__ __half g_bufB[(size_t)Nn * Hh];   // pong
__device__ float  g_pool[Gg * Hh];
__device__ float  g_cnts[Gg];

// ---------------- prep kernels ----------------------------------------------
__global__ void zero_kernel() {
    int i = blockIdx.x * blockDim.x + threadIdx.x;
    if (i < Nn) { g_cnt[i] = 0; g_cursor[i] = 0; }
    if (i < Gg * Hh) g_pool[i] = 0.0f;
    if (i < Gg) g_cnts[i] = 0.0f;
}

__global__ void hist_kernel(const int4* __restrict__ dst4) {
    int e = blockIdx.x * blockDim.x + threadIdx.x;
    if (e < Ee / 4) {
        int4 d = dst4[e];
        if (d.x >= 0 && d.x < Nn) atomicAdd(&g_cnt[d.x], 1);
        if (d.y >= 0 && d.y < Nn) atomicAdd(&g_cnt[d.y], 1);
        if (d.z >= 0 && d.z < Nn) atomicAdd(&g_cnt[d.z], 1);
        if (d.w >= 0 && d.w < Nn) atomicAdd(&g_cnt[d.w], 1);
    }
}

// hierarchical scan: block sums -> scan sums -> per-block rescan
__global__ void scan1_kernel() {
    __shared__ int wsum[8];
    int tid = threadIdx.x, lane = tid & 31, wid = tid >> 5;
    int i = blockIdx.x * 256 + tid;
    int v = (i < Nn) ? g_cnt[i] : 0;
#pragma unroll
    for (int d = 16; d; d >>= 1) v += __shfl_down_sync(0xffffffffu, v, d);
    if (lane == 0) wsum[wid] = v;
    __syncthreads();
    if (tid == 0) {
        int s = 0;
#pragma unroll
        for (int w = 0; w < 8; w++) s += wsum[w];
        g_bsum[blockIdx.x] = s;
    }
}

__global__ void scan2_kernel() {
    __shared__ int s[256];
    int tid = threadIdx.x;
    int v = (tid < NBLK) ? g_bsum[tid] : 0;
    s[tid] = v;
    __syncthreads();
    for (int d = 1; d < 256; d <<= 1) {
        int t = (tid >= d) ? s[tid - d] : 0;
        __syncthreads();
        s[tid] += t;
        __syncthreads();
    }
    if (tid < NBLK) g_boff[tid] = s[tid] - v;   // exclusive
    if (tid == NBLK - 1) g_rowptr[Nn] = s[tid];
}

__global__ void scan3_kernel() {
    __shared__ int wsum[8];
    int tid = threadIdx.x, lane = tid & 31, wid = tid >> 5;
    int i = blockIdx.x * 256 + tid;
    int orig = (i < Nn) ? g_cnt[i] : 0;
    int v = orig;
#pragma unroll
    for (int d = 1; d < 32; d <<= 1) {
        int t = __shfl_up_sync(0xffffffffu, v, d);
        if (lane >= d) v += t;
    }
    if (lane == 31) wsum[wid] = v;
    __syncthreads();
    if (wid == 0 && lane < 8) {
        int s = wsum[lane];
#pragma unroll
        for (int d = 1; d < 8; d <<= 1) {
            int t = __shfl_up_sync(0x000000ffu, s, d);
            if (lane >= d) s += t;
        }
        wsum[lane] = s;
    }
    __syncthreads();
    int prefix = (wid > 0) ? wsum[wid - 1] : 0;
    if (i < Nn) g_rowptr[i] = g_boff[blockIdx.x] + prefix + v - orig;
}

__global__ void fill_kernel(const int4* __restrict__ src4,
                            const int4* __restrict__ dst4) {
    int e = blockIdx.x * blockDim.x + threadIdx.x;
    if (e < Ee / 4) {
        int4 d = dst4[e];
        int4 s = src4[e];
#pragma unroll
        for (int j = 0; j < 4; j++) {
            int dd = (&d.x)[j], ss = (&s.x)[j];
            if (dd >= 0 && dd < Nn && ss >= 0 && ss < Nn) {
                int pos = g_rowptr[dd] + atomicAdd(&g_cursor[dd], 1);
                g_col[pos] = ss;
            }
        }
    }
}

// dinv + per-graph node counts
__global__ void dinv_kernel(const int* __restrict__ batch) {
    int i = blockIdx.x * blockDim.x + threadIdx.x;
    if (i < Nn) {
        g_dinv[i] = rsqrtf((float)(g_cnt[i] + 1));  // +1 self-loop
        int g = batch[i];
        if (g >= 0 && g < Gg) atomicAdd(&g_cnts[g], 1.0f);
    }
}

// transpose + convert W[K][256] (fp32) -> Wt[n][k] (fp16)
__global__ void wconv_kernel(const float* __restrict__ W, int K, int woff) {
    __shared__ float t[32][33];
    int kb = blockIdx.x * 32, nb = blockIdx.y * 32;
    int tx = threadIdx.x, ty = threadIdx.y;   // 32 x 8
    for (int i = ty; i < 32; i += 8)
        t[i][tx] = W[(size_t)(kb + i) * Hh + nb + tx];
    __syncthreads();
    for (int i = ty; i < 32; i += 8)
        g_W16[woff + (size_t)(nb + i) * K + kb + tx] = __float2half_rn(t[tx][i]);
}

// bufA(fp16) = x * dinv[row]   (width Ff); each thread handles 8 floats
__global__ void scale_x_kernel(const float4* __restrict__ x) {
    int idx = blockIdx.x * blockDim.x + threadIdx.x;   // over Nn * 16
    if (idx < Nn * (Ff / 8)) {
        int row = idx >> 4;
        float d = g_dinv[row];
        float4 v0 = x[idx * 2], v1 = x[idx * 2 + 1];
        __half2 h[4];
        h[0] = __floats2half2_rn(v0.x * d, v0.y * d);
        h[1] = __floats2half2_rn(v0.z * d, v0.w * d);
        h[2] = __floats2half2_rn(v1.x * d, v1.y * d);
        h[3] = __floats2half2_rn(v1.z * d, v1.w * d);
        ((uint4*)g_bufA)[idx] = *(uint4*)h;
    }
}

// ---------------- fused aggregate + GEMM kernel ------------------------------
// Phase 1: gather-aggregate 64 node rows into smem As (fp16, pre-scaled form).
// Phase 2: As[64xK] @ Wt^T[Kx256] via m16n8k16 mma, B double-buffered cp.async.
// Epilogue: relu + bias, then *dinv (pre-scale for next layer) or pool atomics.

__device__ __forceinline__ void mma_f16(float* c, const unsigned* a, const unsigned* b) {
    asm volatile(
        "mma.sync.aligned.m16n8k16.row.col.f32.f16.f16.f32 "
        "{%0,%1,%2,%3}, {%4,%5,%6,%7}, {%8,%9}, {%0,%1,%2,%3};"
        : "+f"(c[0]), "+f"(c[1]), "+f"(c[2]), "+f"(c[3])
        : "r"(a[0]), "r"(a[1]), "r"(a[2]), "r"(a[3]), "r"(b[0]), "r"(b[1]));
}

__device__ __forceinline__ void cpa16(unsigned dst, const void* src) {
    asm volatile("cp.async.cg.shared.global [%0], [%1], 16;\n"
                 :: "r"(dst), "l"(src));
}

#define BMF 64
#define BSTR 40    // B smem row stride (halves)

template <int K>
__global__ __launch_bounds__(256, 2)
void fused_kernel(const __half* __restrict__ src, __half* __restrict__ dstFeat,
                  const __half* __restrict__ Wt, const float* __restrict__ bias,
                  int scaleFlag, int poolFlag, const int* __restrict__ batch) {
    constexpr int AST = K + 8;           // A smem row stride (halves)
    constexpr int HPL = K / 32;          // halves per lane in gather (8 or 4)
    extern __shared__ __half sm[];
    __half* As = sm;                                  // [BMF][AST]
    __half* Bs = sm + BMF * AST;                      // [2][256][BSTR]

    int tid = threadIdx.x;
    int warpId = tid >> 5, lane = tid & 31;
    int rowBase = blockIdx.x * BMF;

    // ---- issue first B chunk before gathering (overlaps) ----
    {
        unsigned bD = (unsigned)__cvta_generic_to_shared(&Bs[(size_t)tid * BSTR]);
        const __half* bS = Wt + (size_t)tid * K;
#pragma unroll
        for (int j = 0; j < 4; j++) cpa16(bD + j * 16, bS + j * 8);
        asm volatile("cp.async.commit_group;\n");
    }

    // ---- phase 1: gather-aggregate rows into As ----
    for (int r = warpId; r < BMF; r += 8) {
        int gr = rowBase + r;
        float f[HPL];
        if (gr < Nn) {
            const uint4* hs = (const uint4*)src;   // K=256: row=32 uint4
            const uint2* hs2 = (const uint2*)src;  // K=128: row=32 uint2
            // self-loop
            if (K == 256) {
                uint4 v = hs[(size_t)gr * 32 + lane];
                const unsigned* u = (const unsigned*)&v;
#pragma unroll
                for (int h = 0; h < HPL / 2; h++) {
                    float2 p = __half22float2(*(const __half2*)&u[h]);
                    f[2 * h] = p.x; f[2 * h + 1] = p.y;
                }
            } else {
                uint2 v = hs2[(size_t)gr * 32 + lane];
                const unsigned* u = (const unsigned*)&v;
#pragma unroll
                for (int h = 0; h < HPL / 2; h++) {
                    float2 p = __half22float2(*(const __half2*)&u[h]);
                    f[2 * h] = p.x; f[2 * h + 1] = p.y;
                }
            }
            int beg = g_rowptr[gr], end = g_rowptr[gr + 1];
            int e = beg;
            for (; e + 1 < end; e += 2) {
                int s0 = g_col[e], s1 = g_col[e + 1];
                if (K == 256) {
                    uint4 v0 = hs[(size_t)s0 * 32 + lane];
                    uint4 v1 = hs[(size_t)s1 * 32 + lane];
                    const unsigned* u0 = (const unsigned*)&v0;
                    const unsigned* u1 = (const unsigned*)&v1;
#pragma unroll
                    for (int h = 0; h < HPL / 2; h++) {
                        float2 p0 = __half22float2(*(const __half2*)&u0[h]);
                        float2 p1 = __half22float2(*(const __half2*)&u1[h]);
                        f[2 * h] += p0.x + p1.x;
                        f[2 * h + 1] += p0.y + p1.y;
                    }
                } else {
                    uint2 v0 = hs2[(size_t)s0 * 32 + lane];
                    uint2 v1 = hs2[(size_t)s1 * 32 + lane];
                    const unsigned* u0 = (const unsigned*)&v0;
                    const unsigned* u1 = (const unsigned*)&v1;
#pragma unroll
                    for (int h = 0; h < HPL / 2; h++) {
                        float2 p0 = __half22float2(*(const __half2*)&u0[h]);
                        float2 p1 = __half22float2(*(const __half2*)&u1[h]);
                        f[2 * h] += p0.x + p1.x;
                        f[2 * h + 1] += p0.y + p1.y;
                    }
                }
            }
            if (e < end) {
                int s0 = g_col[e];
                if (K == 256) {
                    uint4 v0 = hs[(size_t)s0 * 32 + lane];
                    const unsigned* u0 = (const unsigned*)&v0;
#pragma unroll
                    for (int h = 0; h < HPL / 2; h++) {
                        float2 p0 = __half22float2(*(const __half2*)&u0[h]);
                        f[2 * h] += p0.x; f[2 * h + 1] += p0.y;
                    }
                } else {
                    uint2 v0 = hs2[(size_t)s0 * 32 + lane];
                    const unsigned* u0 = (const unsigned*)&v0;
#pragma unroll
                    for (int h = 0; h < HPL / 2; h++) {
                        float2 p0 = __half22float2(*(const __half2*)&u0[h]);
                        f[2 * h] += p0.x; f[2 * h + 1] += p0.y;
                    }
                }
            }
            float di = g_dinv[gr];
#pragma unroll
            for (int h = 0; h < HPL; h++) f[h] *= di;
        } else {
#pragma unroll
            for (int h = 0; h < HPL; h++) f[h] = 0.0f;
        }
        // write fp16 row segment to As
        unsigned hw[HPL / 2];
#pragma unroll
        for (int h = 0; h < HPL / 2; h++) {
            __half2 p = __floats2half2_rn(f[2 * h], f[2 * h + 1]);
            hw[h] = *(unsigned*)&p;
        }
        if (K == 256)
            *(uint4*)&As[r * AST + lane * 8] = *(uint4*)hw;
        else
            *(uint2*)&As[r * AST + lane * 4] = *(uint2*)hw;
    }
    __syncthreads();

    // ---- phase 2: mma ----
    int g = lane >> 2, q = lane & 3;
    int warpM = warpId >> 2;          // 0..1 -> 32 rows each
    int warpN = warpId & 3;           // 0..3 -> 64 cols each

    float acc[2][8][4];
#pragma unroll
    for (int mt = 0; mt < 2; mt++)
#pragma unroll
        for (int nt = 0; nt < 8; nt++)
#pragma unroll
            for (int i = 0; i < 4; i++) acc[mt][nt][i] = 0.0f;

    constexpr int NIT = K / 32;
    for (int it = 0; it < NIT; it++) {
        int buf = it & 1;
        if (it + 1 < NIT) {
            unsigned bD = (unsigned)__cvta_generic_to_shared(
                &Bs[(size_t)(1 - buf) * 256 * BSTR + (size_t)tid * BSTR]);
            const __half* bS = Wt + (size_t)tid * K + (it + 1) * 32;
#pragma unroll
            for (int j = 0; j < 4; j++) cpa16(bD + j * 16, bS + j * 8);
            asm volatile("cp.async.commit_group;\n");
            asm volatile("cp.async.wait_group 1;\n");
        } else {
            asm volatile("cp.async.wait_group 0;\n");
        }
        __syncthreads();

        const __half* bsb = Bs + (size_t)buf * 256 * BSTR;
#pragma unroll
        for (int kk = 0; kk < 2; kk++) {
            int kbA = it * 32 + kk * 16;   // within As row
            int kbB = kk * 16;             // within Bs chunk
            unsigned afr[2][4];
#pragma unroll
            for (int mt = 0; mt < 2; mt++) {
                int m = warpM * 32 + mt * 16;
                afr[mt][0] = *(const unsigned*)&As[(m + g) * AST + kbA + 2 * q];
                afr[mt][1] = *(const unsigned*)&As[(m + g + 8) * AST + kbA + 2 * q];
                afr[mt][2] = *(const unsigned*)&As[(m + g) * AST + kbA + 2 * q + 8];
                afr[mt][3] = *(const unsigned*)&As[(m + g + 8) * AST + kbA + 2 * q + 8];
            }
#pragma unroll
            for (int nt = 0; nt < 8; nt++) {
                int n = warpN * 64 + nt * 8;
                unsigned bfr[2];
                bfr[0] = *(const unsigned*)&bsb[(n + g) * BSTR + kbB + 2 * q];
                bfr[1] = *(const unsigned*)&bsb[(n + g) * BSTR + kbB + 2 * q + 8];
#pragma unroll
                for (int mt = 0; mt < 2; mt++)
                    mma_f16(acc[mt][nt], afr[mt], bfr);
            }
        }
        __syncthreads();
    }

    // ---- epilogue ----
#pragma unroll
    for (int mt = 0; mt < 2; mt++) {
        int r0 = rowBase + warpM * 32 + mt * 16 + g;
        int r1 = r0 + 8;
        bool ok0 = r0 < Nn, ok1 = r1 < Nn;
        float sc0 = (ok0 && scaleFlag) ? g_dinv[r0] : 1.0f;
        float sc1 = (ok1 && scaleFlag) ? g_dinv[r1] : 1.0f;
        int gb0 = (ok0 && poolFlag) ? batch[r0] : 0;
        int gb1 = (ok1 && poolFlag) ? batch[r1] : 0;
#pragma unroll
        for (int nt = 0; nt < 8; nt++) {
            int c = warpN * 64 + nt * 8 + 2 * q;
            float bs0 = bias[c], bs1 = bias[c + 1];
            float v00 = fmaxf(acc[mt][nt][0] + bs0, 0.0f) * sc0;
            float v01 = fmaxf(acc[mt][nt][1] + bs1, 0.0f) * sc0;
            float v10 = fmaxf(acc[mt][nt][2] + bs0, 0.0f) * sc1;
            float v11 = fmaxf(acc[mt][nt][3] + bs1, 0.0f) * sc1;
            if (poolFlag) {
                if (ok0) {
                    atomicAdd(&g_pool[gb0 * Hh + c], v00);
                    atomicAdd(&g_pool[gb0 * Hh + c + 1], v01);
                }
                if (ok1) {
                    atomicAdd(&g_pool[gb1 * Hh + c], v10);
                    atomicAdd(&g_pool[gb1 * Hh + c + 1], v11);
                }
            } else {
                if (ok0) {
                    __half2 h = __floats2half2_rn(v00, v01);
                    *(__half2*)&dstFeat[(size_t)r0 * Hh + c] = h;
                }
                if (ok1) {
                    __half2 h = __floats2half2_rn(v10, v11);
                    *(__half2*)&dstFeat[(size_t)r1 * Hh + c] = h;
                }
            }
        }
    }
}

// ---------------- output head -------------------------------------------------
__global__ void out_kernel(const float* __restrict__ Wout,
                           const float* __restrict__ bout,
                           float* __restrict__ out) {
    int g = blockIdx.x;
    int lane = threadIdx.x;                 // 32 threads
    float inv = 1.0f / fmaxf(g_cnts[g], 1.0f);
    float p[8];
#pragma unroll
    for (int v = 0; v < 8; v++) p[v] = g_pool[g * Hh + v * 32 + lane] * inv;
#pragma unroll
    for (int t = 0; t < Tt; t++) {
        float s = 0.0f;
#pragma unroll
        for (int v = 0; v < 8; v++) s += p[v] * Wout[(v * 32 + lane) * Tt + t];
#pragma unroll
        for (int off = 16; off; off >>= 1) s += __shfl_down_sync(0xffffffffu, s, off);
        if (lane == 0) out[g * Tt + t] = s + bout[t];
    }
}

// ---------------- launch -----------------------------------------------------
extern "C" void kernel_launch(void* const* d_in, const int* in_sizes, int n_in,
                              void* d_out, int out_size) {
    const float* x    = (const float*)d_in[0];
    const int*   ei   = (const int*)d_in[1];   // [2, E] int32
    const int*   bat  = (const int*)d_in[2];
    const float* W0 = (const float*)d_in[3];  const float* b0 = (const float*)d_in[4];
    const float* W1 = (const float*)d_in[5];  const float* b1 = (const float*)d_in[6];
    const float* W2 = (const float*)d_in[7];  const float* b2 = (const float*)d_in[8];
    const float* W3 = (const float*)d_in[9];  const float* b3 = (const float*)d_in[10];
    const float* Wout = (const float*)d_in[11]; const float* bout = (const float*)d_in[12];
    float* out = (float*)d_out;

    const int* src = ei;
    const int* dst = ei + Ee;

    // smem sizes
    const int smem256 = (BMF * (256 + 8) + 2 * 256 * BSTR) * 2;   // 74752 B
    const int smem128 = (BMF * (128 + 8) + 2 * 256 * BSTR) * 2;   // 58368 B
    cudaFuncSetAttribute(fused_kernel<256>,
                         cudaFuncAttributeMaxDynamicSharedMemorySize, smem256);
    cudaFuncSetAttribute(fused_kernel<128>,
                         cudaFuncAttributeMaxDynamicSharedMemorySize, smem128);

    // prep
    zero_kernel<<<(Gg * Hh + 255) / 256, 256>>>();
    hist_kernel<<<(Ee / 4 + 255) / 256, 256>>>((const int4*)dst);
    scan1_kernel<<<NBLK, 256>>>();
    scan2_kernel<<<1, 256>>>();
    scan3_kernel<<<NBLK, 256>>>();
    fill_kernel<<<(Ee / 4 + 255) / 256, 256>>>((const int4*)src, (const int4*)dst);
    dinv_kernel<<<(Nn + 255) / 256, 256>>>(bat);
    // weight transpose+convert
    dim3 wcb(32, 8);
    wconv_kernel<<<dim3(Ff / 32, Hh / 32), wcb>>>(W0, Ff, W0OFF);
    wconv_kernel<<<dim3(Hh / 32, Hh / 32), wcb>>>(W1, Hh, W1OFF);
    wconv_kernel<<<dim3(Hh / 32, Hh / 32), wcb>>>(W2, Hh, W2OFF);
    wconv_kernel<<<dim3(Hh / 32, Hh / 32), wcb>>>(W3, Hh, W3OFF);
    scale_x_kernel<<<(Nn * (Ff / 8) + 255) / 256, 256>>>((const float4*)x);

    __half* W16;
    cudaGetSymbolAddress((void**)&W16, g_W16);
    __half* bufA;
    cudaGetSymbolAddress((void**)&bufA, g_bufA);
    __half* bufB;
    cudaGetSymbolAddress((void**)&bufB, g_bufB);

    int grid = (Nn + BMF - 1) / BMF;   // 782

    // layer 0 (K=128): bufA -> bufB
    fused_kernel<128><<<grid, 256, smem128>>>(bufA, bufB, W16 + W0OFF, b0, 1, 0, bat);
    // layer 1: bufB -> bufA
    fused_kernel<256><<<grid, 256, smem256>>>(bufB, bufA, W16 + W1OFF, b1, 1, 0, bat);
    // layer 2: bufA -> bufB
    fused_kernel<256><<<grid, 256, smem256>>>(bufA, bufB, W16 + W2OFF, b2, 1, 0, bat);
    // layer 3: bufB -> pool (fused mean-pool accumulation)
    fused_kernel<256><<<grid, 256, smem256>>>(bufB, bufA, W16 + W3OFF, b3, 0, 1, bat);

    // head
    out_kernel<<<Gg, 32>>>(Wout, bout, out);
}

// round 7
// speedup vs baseline: 1.4489x; 1.4489x over previous
#include <cuda_runtime.h>
#include <cuda_fp16.h>

// Problem constants (fixed by the dataset)
#define Nn 50000
#define Ee 800000
#define Ff 128
#define Hh 256
#define Gg 512
#define Tt 5

#define NBLK 196   // ceil(Nn/256) scan blocks

// W16 offsets (halves): W0t 256x128, W1..3t 256x256
#define W0OFF 0
#define W1OFF 32768
#define W2OFF 98304
#define W3OFF 163840

// ---------------- scratch (device globals; no allocations allowed) ----------
__device__ int    g_cnt[Nn];
__device__ int    g_rowptr[Nn + 1];
__device__ int    g_cursor[Nn];
__device__ int    g_col[Ee];
__device__ float  g_dinv[Nn];
__device__ int    g_bsum[NBLK];
__device__ int    g_boff[NBLK];
__device__ __half g_W16[229376];             // transposed fp16 weights [n][k]
__device__ __half g_bufA[(size_t)Nn * Hh];   // ping (features, fp16)
__device__ __half g_bufB[(size_t)Nn * Hh];   // pong (aggregation output, fp16)
__device__ float  g_pool[Gg * Hh];
__device__ float  g_cnts[Gg];

// ---------------- prep kernels ----------------------------------------------
__global__ void zero_kernel() {
    int i = blockIdx.x * blockDim.x + threadIdx.x;
    if (i < Nn) { g_cnt[i] = 0; g_cursor[i] = 0; }
    if (i < Gg * Hh) g_pool[i] = 0.0f;
    if (i < Gg) g_cnts[i] = 0.0f;
}

__global__ void hist_kernel(const int4* __restrict__ dst4) {
    int e = blockIdx.x * blockDim.x + threadIdx.x;
    if (e < Ee / 4) {
        int4 d = dst4[e];
        if (d.x >= 0 && d.x < Nn) atomicAdd(&g_cnt[d.x], 1);
        if (d.y >= 0 && d.y < Nn) atomicAdd(&g_cnt[d.y], 1);
        if (d.z >= 0 && d.z < Nn) atomicAdd(&g_cnt[d.z], 1);
        if (d.w >= 0 && d.w < Nn) atomicAdd(&g_cnt[d.w], 1);
    }
}

// hierarchical scan: block sums -> scan sums -> per-block rescan
__global__ void scan1_kernel() {
    __shared__ int wsum[8];
    int tid = threadIdx.x, lane = tid & 31, wid = tid >> 5;
    int i = blockIdx.x * 256 + tid;
    int v = (i < Nn) ? g_cnt[i] : 0;
#pragma unroll
    for (int d = 16; d; d >>= 1) v += __shfl_down_sync(0xffffffffu, v, d);
    if (lane == 0) wsum[wid] = v;
    __syncthreads();
    if (tid == 0) {
        int s = 0;
#pragma unroll
        for (int w = 0; w < 8; w++) s += wsum[w];
        g_bsum[blockIdx.x] = s;
    }
}

__global__ void scan2_kernel() {
    __shared__ int s[256];
    int tid = threadIdx.x;
    int v = (tid < NBLK) ? g_bsum[tid] : 0;
    s[tid] = v;
    __syncthreads();
    for (int d = 1; d < 256; d <<= 1) {
        int t = (tid >= d) ? s[tid - d] : 0;
        __syncthreads();
        s[tid] += t;
        __syncthreads();
    }
    if (tid < NBLK) g_boff[tid] = s[tid] - v;   // exclusive
    if (tid == NBLK - 1) g_rowptr[Nn] = s[tid];
}

__global__ void scan3_kernel() {
    __shared__ int wsum[8];
    int tid = threadIdx.x, lane = tid & 31, wid = tid >> 5;
    int i = blockIdx.x * 256 + tid;
    int orig = (i < Nn) ? g_cnt[i] : 0;
    int v = orig;
#pragma unroll
    for (int d = 1; d < 32; d <<= 1) {
        int t = __shfl_up_sync(0xffffffffu, v, d);
        if (lane >= d) v += t;
    }
    if (lane == 31) wsum[wid] = v;
    __syncthreads();
    if (wid == 0 && lane < 8) {
        int s = wsum[lane];
#pragma unroll
        for (int d = 1; d < 8; d <<= 1) {
            int t = __shfl_up_sync(0x000000ffu, s, d);
            if (lane >= d) s += t;
        }
        wsum[lane] = s;
    }
    __syncthreads();
    int prefix = (wid > 0) ? wsum[wid - 1] : 0;
    if (i < Nn) g_rowptr[i] = g_boff[blockIdx.x] + prefix + v - orig;
}

__global__ void fill_kernel(const int4* __restrict__ src4,
                            const int4* __restrict__ dst4) {
    int e = blockIdx.x * blockDim.x + threadIdx.x;
    if (e < Ee / 4) {
        int4 d = dst4[e];
        int4 s = src4[e];
#pragma unroll
        for (int j = 0; j < 4; j++) {
            int dd = (&d.x)[j], ss = (&s.x)[j];
            if (dd >= 0 && dd < Nn && ss >= 0 && ss < Nn) {
                int pos = g_rowptr[dd] + atomicAdd(&g_cursor[dd], 1);
                g_col[pos] = ss;
            }
        }
    }
}

// dinv + per-graph node counts
__global__ void dinv_kernel(const int* __restrict__ batch) {
    int i = blockIdx.x * blockDim.x + threadIdx.x;
    if (i < Nn) {
        g_dinv[i] = rsqrtf((float)(g_cnt[i] + 1));  // +1 self-loop
        int g = batch[i];
        if (g >= 0 && g < Gg) atomicAdd(&g_cnts[g], 1.0f);
    }
}

// transpose + convert W[K][256] (fp32) -> Wt[n][k] (fp16)
__global__ void wconv_kernel(const float* __restrict__ W, int K, int woff) {
    __shared__ float t[32][33];
    int kb = blockIdx.x * 32, nb = blockIdx.y * 32;
    int tx = threadIdx.x, ty = threadIdx.y;   // 32 x 8
    for (int i = ty; i < 32; i += 8)
        t[i][tx] = W[(size_t)(kb + i) * Hh + nb + tx];
    __syncthreads();
    for (int i = ty; i < 32; i += 8)
        g_W16[woff + (size_t)(nb + i) * K + kb + tx] = __float2half_rn(t[tx][i]);
}

// bufA(fp16) = x * dinv[row]   (width Ff); each thread handles 8 floats
__global__ void scale_x_kernel(const float4* __restrict__ x) {
    int idx = blockIdx.x * blockDim.x + threadIdx.x;   // over Nn * 16
    if (idx < Nn * (Ff / 8)) {
        int row = idx >> 4;
        float d = g_dinv[row];
        float4 v0 = x[idx * 2], v1 = x[idx * 2 + 1];
        __half2 h[4];
        h[0] = __floats2half2_rn(v0.x * d, v0.y * d);
        h[1] = __floats2half2_rn(v0.z * d, v0.w * d);
        h[2] = __floats2half2_rn(v1.x * d, v1.y * d);
        h[3] = __floats2half2_rn(v1.z * d, v1.w * d);
        ((uint4*)g_bufA)[idx] = *(uint4*)h;
    }
}

// ---------------- aggregation (fp16 in, fp32 accum, fp16 out) ---------------
template <int UC> struct VecT;
template <> struct VecT<2> { using T = uint2; };
template <> struct VecT<4> { using T = uint4; };

template <int VH>
__global__ void agg_kernel() {
    constexpr int UC = VH / 2;
    using V = typename VecT<UC>::T;
    int warp = (blockIdx.x * blockDim.x + threadIdx.x) >> 5;
    int lane = threadIdx.x & 31;
    if (warp >= Nn) return;
    const V* __restrict__ hs = (const V*)g_bufA;   // row = 32 V units
    V* __restrict__ outp = (V*)g_bufB;

    float f[VH];
    {
        V v = hs[(size_t)warp * 32 + lane];        // self-loop term
        const unsigned* u = (const unsigned*)&v;
#pragma unroll
        for (int h = 0; h < UC; h++) {
            float2 p = __half22float2(*(const __half2*)&u[h]);
            f[2 * h] = p.x; f[2 * h + 1] = p.y;
        }
    }

    int beg = g_rowptr[warp], end = g_rowptr[warp + 1];
    int e = beg;
    for (; e + 1 < end; e += 2) {
        int s0 = g_col[e], s1 = g_col[e + 1];
        V v0 = hs[(size_t)s0 * 32 + lane];
        V v1 = hs[(size_t)s1 * 32 + lane];
        const unsigned* u0 = (const unsigned*)&v0;
        const unsigned* u1 = (const unsigned*)&v1;
#pragma unroll
        for (int h = 0; h < UC; h++) {
            float2 p0 = __half22float2(*(const __half2*)&u0[h]);
            float2 p1 = __half22float2(*(const __half2*)&u1[h]);
            f[2 * h] += p0.x + p1.x;
            f[2 * h + 1] += p0.y + p1.y;
        }
    }
    if (e < end) {
        int s0 = g_col[e];
        V v0 = hs[(size_t)s0 * 32 + lane];
        const unsigned* u0 = (const unsigned*)&v0;
#pragma unroll
        for (int h = 0; h < UC; h++) {
            float2 p0 = __half22float2(*(const __half2*)&u0[h]);
            f[2 * h] += p0.x;
            f[2 * h + 1] += p0.y;
        }
    }
    float di = g_dinv[warp];
    V ov;
    unsigned* ou = (unsigned*)&ov;
#pragma unroll
    for (int h = 0; h < UC; h++) {
        __half2 p = __floats2half2_rn(f[2 * h] * di, f[2 * h + 1] * di);
        ou[h] = *(unsigned*)&p;
    }
    outp[(size_t)warp * 32 + lane] = ov;
}

// ---------------- fp16 tensor-core GEMM (R4 structure, fp16 Wt loads) -------
#define BM 128
#define BN 128
#define BK 32
#define ASTR 40    // smem row stride in halves; conflict-free fragment loads

__device__ __forceinline__ void mma_f16(float* c, const unsigned* a, const unsigned* b) {
    asm volatile(
        "mma.sync.aligned.m16n8k16.row.col.f32.f16.f16.f32 "
        "{%0,%1,%2,%3}, {%4,%5,%6,%7}, {%8,%9}, {%0,%1,%2,%3};"
        : "+f"(c[0]), "+f"(c[1]), "+f"(c[2]), "+f"(c[3])
        : "r"(a[0]), "r"(a[1]), "r"(a[2]), "r"(a[3]), "r"(b[0]), "r"(b[1]));
}

__global__ __launch_bounds__(256)
void gemm_f16_kernel(const __half* __restrict__ Wt,   // [256][K] fp16
                     const float* __restrict__ bias,
                     int K, int scaleFlag, int poolFlag,
                     const int* __restrict__ batch) {
    __shared__ alignas(16) __half As[BM][ASTR];   // [m][k]
    __shared__ alignas(16) __half Bs[BN][ASTR];   // [n][k]

    const __half* __restrict__ A = g_bufB;
    __half* __restrict__ C = g_bufA;

    int tid = threadIdx.x;
    int warpId = tid >> 5, lane = tid & 31;
    int g = lane >> 2, q = lane & 3;
    int warpM = warpId >> 2;          // 0..1  -> 64 rows each
    int warpN = warpId & 3;           // 0..3  -> 32 cols each
    int rowBase = blockIdx.x * BM;
    int colBase = blockIdx.y * BN;

    float acc[4][4][4];
#pragma unroll
    for (int mt = 0; mt < 4; mt++)
#pragma unroll
        for (int nt = 0; nt < 4; nt++)
#pragma unroll
            for (int i = 0; i < 4; i++) acc[mt][nt][i] = 0.0f;

    int aRow = tid >> 1;              // 0..127
    int aKoff = (tid & 1) * 16;       // halves
    int bN = tid & 127;
    int bKoff = (tid >> 7) * 16;      // halves

    int gr = rowBase + aRow;
    bool aOk = gr < Nn;
    const __half* aSrc = A + (size_t)gr * K + aKoff;
    const __half* bSrc = Wt + (size_t)(colBase + bN) * K + bKoff;

    for (int k0 = 0; k0 < K; k0 += BK) {
        // ---- A tile (fp16 global -> smem) ----
        uint4 av0 = make_uint4(0, 0, 0, 0), av1 = av0;
        if (aOk) {
            const uint4* ap = (const uint4*)(aSrc + k0);
            av0 = ap[0]; av1 = ap[1];
        }
        *(uint4*)&As[aRow][aKoff] = av0;
        *(uint4*)&As[aRow][aKoff + 8] = av1;
        // ---- B tile (fp16 pre-transposed global -> smem) ----
        const uint4* bp = (const uint4*)(bSrc + k0);
        uint4 bv0 = bp[0], bv1 = bp[1];
        *(uint4*)&Bs[bN][bKoff] = bv0;
        *(uint4*)&Bs[bN][bKoff + 8] = bv1;
        __syncthreads();

#pragma unroll
        for (int kk = 0; kk < 2; kk++) {
            int kb = kk * 16;
            unsigned afr[4][4];
#pragma unroll
            for (int mt = 0; mt < 4; mt++) {
                int m = warpM * 64 + mt * 16;
                afr[mt][0] = *(const unsigned*)&As[m + g][kb + 2 * q];
                afr[mt][1] = *(const unsigned*)&As[m + g + 8][kb + 2 * q];
                afr[mt][2] = *(const unsigned*)&As[m + g][kb + 2 * q + 8];
                afr[mt][3] = *(const unsigned*)&As[m + g + 8][kb + 2 * q + 8];
            }
#pragma unroll
            for (int nt = 0; nt < 4; nt++) {
                int n = warpN * 32 + nt * 8;
                unsigned bfr[2];
                bfr[0] = *(const unsigned*)&Bs[n + g][kb + 2 * q];
                bfr[1] = *(const unsigned*)&Bs[n + g][kb + 2 * q + 8];
#pragma unroll
                for (int mt = 0; mt < 4; mt++)
                    mma_f16(acc[mt][nt], afr[mt], bfr);
            }
        }
        __syncthreads();
    }

    // ---- epilogue ----
#pragma unroll
    for (int mt = 0; mt < 4; mt++) {
        int r0 = rowBase + warpM * 64 + mt * 16 + g;
        int r1 = r0 + 8;
        bool ok0 = r0 < Nn, ok1 = r1 < Nn;
        float sc0 = (ok0 && scaleFlag) ? g_dinv[r0] : 1.0f;
        float sc1 = (ok1 && scaleFlag) ? g_dinv[r1] : 1.0f;
        int gb0 = (ok0 && poolFlag) ? batch[r0] : 0;
        int gb1 = (ok1 && poolFlag) ? batch[r1] : 0;
#pragma unroll
        for (int nt = 0; nt < 4; nt++) {
            int c = colBase + warpN * 32 + nt * 8 + 2 * q;
            float bs0 = bias[c], bs1 = bias[c + 1];
            float v00 = fmaxf(acc[mt][nt][0] + bs0, 0.0f) * sc0;
            float v01 = fmaxf(acc[mt][nt][1] + bs1, 0.0f) * sc0;
            float v10 = fmaxf(acc[mt][nt][2] + bs0, 0.0f) * sc1;
            float v11 = fmaxf(acc[mt][nt][3] + bs1, 0.0f) * sc1;
            if (poolFlag) {
                if (ok0) {
                    atomicAdd(&g_pool[gb0 * Hh + c], v00);
                    atomicAdd(&g_pool[gb0 * Hh + c + 1], v01);
                }
                if (ok1) {
                    atomicAdd(&g_pool[gb1 * Hh + c], v10);
                    atomicAdd(&g_pool[gb1 * Hh + c + 1], v11);
                }
            } else {
                if (ok0) {
                    __half2 h = __floats2half2_rn(v00, v01);
                    *(__half2*)&C[(size_t)r0 * Hh + c] = h;
                }
                if (ok1) {
                    __half2 h = __floats2half2_rn(v10, v11);
                    *(__half2*)&C[(size_t)r1 * Hh + c] = h;
                }
            }
        }
    }
}

// ---------------- output head -------------------------------------------------
__global__ void out_kernel(const float* __restrict__ Wout,
                           const float* __restrict__ bout,
                           float* __restrict__ out) {
    int g = blockIdx.x;
    int lane = threadIdx.x;                 // 32 threads
    float inv = 1.0f / fmaxf(g_cnts[g], 1.0f);
    float p[8];
#pragma unroll
    for (int v = 0; v < 8; v++) p[v] = g_pool[g * Hh + v * 32 + lane] * inv;
#pragma unroll
    for (int t = 0; t < Tt; t++) {
        float s = 0.0f;
#pragma unroll
        for (int v = 0; v < 8; v++) s += p[v] * Wout[(v * 32 + lane) * Tt + t];
#pragma unroll
        for (int off = 16; off; off >>= 1) s += __shfl_down_sync(0xffffffffu, s, off);
        if (lane == 0) out[g * Tt + t] = s + bout[t];
    }
}

// ---------------- launch -----------------------------------------------------
extern "C" void kernel_launch(void* const* d_in, const int* in_sizes, int n_in,
                              void* d_out, int out_size) {
    const float* x    = (const float*)d_in[0];
    const int*   ei   = (const int*)d_in[1];   // [2, E] int32
    const int*   bat  = (const int*)d_in[2];
    const float* W0 = (const float*)d_in[3];  const float* b0 = (const float*)d_in[4];
    const float* W1 = (const float*)d_in[5];  const float* b1 = (const float*)d_in[6];
    const float* W2 = (const float*)d_in[7];  const float* b2 = (const float*)d_in[8];
    const float* W3 = (const float*)d_in[9];  const float* b3 = (const float*)d_in[10];
    const float* Wout = (const float*)d_in[11]; const float* bout = (const float*)d_in[12];
    float* out = (float*)d_out;

    const int* src = ei;
    const int* dst = ei + Ee;

    // prep
    zero_kernel<<<(Gg * Hh + 255) / 256, 256>>>();
    hist_kernel<<<(Ee / 4 + 255) / 256, 256>>>((const int4*)dst);
    scan1_kernel<<<NBLK, 256>>>();
    scan2_kernel<<<1, 256>>>();
    scan3_kernel<<<NBLK, 256>>>();
    fill_kernel<<<(Ee / 4 + 255) / 256, 256>>>((const int4*)src, (const int4*)dst);
    dinv_kernel<<<(Nn + 255) / 256, 256>>>(bat);
    // weight transpose+convert
    dim3 wcb(32, 8);
    wconv_kernel<<<dim3(Ff / 32, Hh / 32), wcb>>>(W0, Ff, W0OFF);
    wconv_kernel<<<dim3(Hh / 32, Hh / 32), wcb>>>(W1, Hh, W1OFF);
    wconv_kernel<<<dim3(Hh / 32, Hh / 32), wcb>>>(W2, Hh, W2OFF);
    wconv_kernel<<<dim3(Hh / 32, Hh / 32), wcb>>>(W3, Hh, W3OFF);
    scale_x_kernel<<<(Nn * (Ff / 8) + 255) / 256, 256>>>((const float4*)x);

    dim3 gemmGrid((Nn + BM - 1) / BM, Hh / BN);
    int aggBlocks = (Nn * 32 + 255) / 256;

    __half* W16;
    cudaGetSymbolAddress((void**)&W16, g_W16);

    // layer 0 (K=128)
    agg_kernel<4><<<aggBlocks, 256>>>();
    gemm_f16_kernel<<<gemmGrid, 256>>>(W16 + W0OFF, b0, Ff, 1, 0, bat);
    // layer 1
    agg_kernel<8><<<aggBlocks, 256>>>();
    gemm_f16_kernel<<<gemmGrid, 256>>>(W16 + W1OFF, b1, Hh, 1, 0, bat);
    // layer 2
    agg_kernel<8><<<aggBlocks, 256>>>();
    gemm_f16_kernel<<<gemmGrid, 256>>>(W16 + W2OFF, b2, Hh, 1, 0, bat);
    // layer 3: no dinv pre-scale; fused mean-pool accumulation
    agg_kernel<8><<<aggBlocks, 256>>>();
    gemm_f16_kernel<<<gemmGrid, 256>>>(W16 + W3OFF, b3, Hh, 0, 1, bat);

    // head
    out_kernel<<<Gg, 32>>>(Wout, bout, out);
}

// round 8
// speedup vs baseline: 1.6924x; 1.1681x over previous
#include <cuda_runtime.h>
#include <cuda_fp16.h>

// Problem constants (fixed by the dataset)
#define Nn 50000
#define Ee 800000
#define Ff 128
#define Hh 256
#define Gg 512
#define Tt 5

#define NBLK 196   // ceil(Nn/256) scan blocks

// W16 offsets (halves), [k][n] layout (row-major, n stride 256)
#define W0OFF 0
#define W1OFF 32768
#define W2OFF 98304
#define W3OFF 163840
#define WTOT  229376

// ---------------- scratch (device globals; no allocations allowed) ----------
__device__ int    g_cnt[Nn];
__device__ int    g_rowptr[Nn + 1];
__device__ int    g_cursor[Nn];
__device__ int    g_col[Ee];
__device__ float  g_dinv[Nn];
__device__ int    g_bsum[NBLK];
__device__ int    g_boff[NBLK];
__device__ __half g_W16[WTOT];               // fp16 weights, [k][n]
__device__ __half g_bufA[(size_t)Nn * Hh];   // ping (features, fp16)
__device__ __half g_bufB[(size_t)Nn * Hh];   // pong (aggregation output, fp16)
__device__ float  g_pool[Gg * Hh];
__device__ float  g_cnts[Gg];

// ---------------- prep kernels ----------------------------------------------
__global__ void zero_kernel() {
    int i = blockIdx.x * blockDim.x + threadIdx.x;
    if (i < Nn) g_cnt[i] = 0;
    if (i < Gg * Hh) g_pool[i] = 0.0f;
    if (i < Gg) g_cnts[i] = 0.0f;
}

__global__ void hist_kernel(const int4* __restrict__ dst4) {
    int e = blockIdx.x * blockDim.x + threadIdx.x;
    if (e < Ee / 4) {
        int4 d = dst4[e];
        if (d.x >= 0 && d.x < Nn) atomicAdd(&g_cnt[d.x], 1);
        if (d.y >= 0 && d.y < Nn) atomicAdd(&g_cnt[d.y], 1);
        if (d.z >= 0 && d.z < Nn) atomicAdd(&g_cnt[d.z], 1);
        if (d.w >= 0 && d.w < Nn) atomicAdd(&g_cnt[d.w], 1);
    }
}

// hierarchical scan: block sums -> scan sums -> per-block rescan
__global__ void scan1_kernel() {
    __shared__ int wsum[8];
    int tid = threadIdx.x, lane = tid & 31, wid = tid >> 5;
    int i = blockIdx.x * 256 + tid;
    int v = (i < Nn) ? g_cnt[i] : 0;
#pragma unroll
    for (int d = 16; d; d >>= 1) v += __shfl_down_sync(0xffffffffu, v, d);
    if (lane == 0) wsum[wid] = v;
    __syncthreads();
    if (tid == 0) {
        int s = 0;
#pragma unroll
        for (int w = 0; w < 8; w++) s += wsum[w];
        g_bsum[blockIdx.x] = s;
    }
}

__global__ void scan2_kernel() {
    __shared__ int s[256];
    int tid = threadIdx.x;
    int v = (tid < NBLK) ? g_bsum[tid] : 0;
    s[tid] = v;
    __syncthreads();
    for (int d = 1; d < 256; d <<= 1) {
        int t = (tid >= d) ? s[tid - d] : 0;
        __syncthreads();
        s[tid] += t;
        __syncthreads();
    }
    if (tid < NBLK) g_boff[tid] = s[tid] - v;   // exclusive
    if (tid == NBLK - 1) g_rowptr[Nn] = s[tid];
}

// scan3 also: dinv, per-graph counts, cursor zero (folds old dinv_kernel)
__global__ void scan3_kernel(const int* __restrict__ batch) {
    __shared__ int wsum[8];
    int tid = threadIdx.x, lane = tid & 31, wid = tid >> 5;
    int i = blockIdx.x * 256 + tid;
    int orig = (i < Nn) ? g_cnt[i] : 0;
    int v = orig;
#pragma unroll
    for (int d = 1; d < 32; d <<= 1) {
        int t = __shfl_up_sync(0xffffffffu, v, d);
        if (lane >= d) v += t;
    }
    if (lane == 31) wsum[wid] = v;
    __syncthreads();
    if (wid == 0 && lane < 8) {
        int s = wsum[lane];
#pragma unroll
        for (int d = 1; d < 8; d <<= 1) {
            int t = __shfl_up_sync(0x000000ffu, s, d);
            if (lane >= d) s += t;
        }
        wsum[lane] = s;
    }
    __syncthreads();
    int prefix = (wid > 0) ? wsum[wid - 1] : 0;
    if (i < Nn) {
        g_rowptr[i] = g_boff[blockIdx.x] + prefix + v - orig;
        g_cursor[i] = 0;
        g_dinv[i] = rsqrtf((float)(orig + 1));   // +1 self-loop
        int g = batch[i];
        if (g >= 0 && g < Gg) atomicAdd(&g_cnts[g], 1.0f);
    }
}

__global__ void fill_kernel(const int4* __restrict__ src4,
                            const int4* __restrict__ dst4) {
    int e = blockIdx.x * blockDim.x + threadIdx.x;
    if (e < Ee / 4) {
        int4 d = dst4[e];
        int4 s = src4[e];
#pragma unroll
        for (int j = 0; j < 4; j++) {
            int dd = (&d.x)[j], ss = (&s.x)[j];
            if (dd >= 0 && dd < Nn && ss >= 0 && ss < Nn) {
                int pos = g_rowptr[dd] + atomicAdd(&g_cursor[dd], 1);
                g_col[pos] = ss;
            }
        }
    }
}

// elementwise convert all 4 weight matrices fp32 -> fp16, [k][n] preserved
__global__ void wconv_all_kernel(const float* __restrict__ W0,
                                 const float* __restrict__ W1,
                                 const float* __restrict__ W2,
                                 const float* __restrict__ W3) {
    int i = blockIdx.x * blockDim.x + threadIdx.x;
    if (i >= WTOT) return;
    const float* p; int off;
    if (i < W1OFF)      { p = W0; off = W0OFF; }
    else if (i < W2OFF) { p = W1; off = W1OFF; }
    else if (i < W3OFF) { p = W2; off = W2OFF; }
    else                { p = W3; off = W3OFF; }
    g_W16[i] = __float2half_rn(p[i - off]);
}

// bufA(fp16) = x * dinv[row]   (width Ff); each thread handles 8 floats
__global__ void scale_x_kernel(const float4* __restrict__ x) {
    int idx = blockIdx.x * blockDim.x + threadIdx.x;   // over Nn * 16
    if (idx < Nn * (Ff / 8)) {
        int row = idx >> 4;
        float d = g_dinv[row];
        float4 v0 = x[idx * 2], v1 = x[idx * 2 + 1];
        __half2 h[4];
        h[0] = __floats2half2_rn(v0.x * d, v0.y * d);
        h[1] = __floats2half2_rn(v0.z * d, v0.w * d);
        h[2] = __floats2half2_rn(v1.x * d, v1.y * d);
        h[3] = __floats2half2_rn(v1.z * d, v1.w * d);
        ((uint4*)g_bufA)[idx] = *(uint4*)h;
    }
}

// ---------------- aggregation (fp16 in, fp32 accum, fp16 out) ---------------
template <int UC> struct VecT;
template <> struct VecT<2> { using T = uint2; };
template <> struct VecT<4> { using T = uint4; };

template <int VH>
__global__ void agg_kernel() {
    constexpr int UC = VH / 2;
    using V = typename VecT<UC>::T;
    int warp = (blockIdx.x * blockDim.x + threadIdx.x) >> 5;
    int lane = threadIdx.x & 31;
    if (warp >= Nn) return;
    const V* __restrict__ hs = (const V*)g_bufA;   // row = 32 V units
    V* __restrict__ outp = (V*)g_bufB;

    float f[VH];
    {
        V v = hs[(size_t)warp * 32 + lane];        // self-loop term
        const unsigned* u = (const unsigned*)&v;
#pragma unroll
        for (int h = 0; h < UC; h++) {
            float2 p = __half22float2(*(const __half2*)&u[h]);
            f[2 * h] = p.x; f[2 * h + 1] = p.y;
        }
    }

    int beg = g_rowptr[warp], end = g_rowptr[warp + 1];
    int e = beg;
    for (; e + 1 < end; e += 2) {
        int s0 = g_col[e], s1 = g_col[e + 1];
        V v0 = hs[(size_t)s0 * 32 + lane];
        V v1 = hs[(size_t)s1 * 32 + lane];
        const unsigned* u0 = (const unsigned*)&v0;
        const unsigned* u1 = (const unsigned*)&v1;
#pragma unroll
        for (int h = 0; h < UC; h++) {
            float2 p0 = __half22float2(*(const __half2*)&u0[h]);
            float2 p1 = __half22float2(*(const __half2*)&u1[h]);
            f[2 * h] += p0.x + p1.x;
            f[2 * h + 1] += p0.y + p1.y;
        }
    }
    if (e < end) {
        int s0 = g_col[e];
        V v0 = hs[(size_t)s0 * 32 + lane];
        const unsigned* u0 = (const unsigned*)&v0;
#pragma unroll
        for (int h = 0; h < UC; h++) {
            float2 p0 = __half22float2(*(const __half2*)&u0[h]);
            f[2 * h] += p0.x;
            f[2 * h + 1] += p0.y;
        }
    }
    float di = g_dinv[warp];
    V ov;
    unsigned* ou = (unsigned*)&ov;
#pragma unroll
    for (int h = 0; h < UC; h++) {
        __half2 p = __floats2half2_rn(f[2 * h] * di, f[2 * h + 1] * di);
        ou[h] = *(unsigned*)&p;
    }
    outp[(size_t)warp * 32 + lane] = ov;
}

// ---------------- fp16 tensor-core GEMM (R4 structure, k-major B + ldmatrix) -
#define BM 128
#define BN 128
#define BK 32
#define ASTR 40    // A smem row stride (halves)
#define BNP 136    // B smem row stride (halves); 136 = 68 words = 4 mod 32

__device__ __forceinline__ void mma_f16(float* c, const unsigned* a, const unsigned* b) {
    asm volatile(
        "mma.sync.aligned.m16n8k16.row.col.f32.f16.f16.f32 "
        "{%0,%1,%2,%3}, {%4,%5,%6,%7}, {%8,%9}, {%0,%1,%2,%3};"
        : "+f"(c[0]), "+f"(c[1]), "+f"(c[2]), "+f"(c[3])
        : "r"(a[0]), "r"(a[1]), "r"(a[2]), "r"(a[3]), "r"(b[0]), "r"(b[1]));
}

__device__ __forceinline__ void ldsm_x2_trans(unsigned& r0, unsigned& r1, const void* p) {
    unsigned addr = (unsigned)__cvta_generic_to_shared(p);
    asm volatile("ldmatrix.sync.aligned.m8n8.x2.trans.shared.b16 {%0,%1}, [%2];"
                 : "=r"(r0), "=r"(r1) : "r"(addr));
}

__global__ __launch_bounds__(256)
void gemm_f16_kernel(const __half* __restrict__ Wk,   // [K][256] fp16
                     const float* __restrict__ bias,
                     int K, int scaleFlag, int poolFlag,
                     const int* __restrict__ batch) {
    __shared__ alignas(16) __half As[BM][ASTR];   // [m][k]
    __shared__ alignas(16) __half Bs[BK][BNP];    // [k][n]

    const __half* __restrict__ A = g_bufB;
    __half* __restrict__ C = g_bufA;

    int tid = threadIdx.x;
    int warpId = tid >> 5, lane = tid & 31;
    int g = lane >> 2, q = lane & 3;
    int warpM = warpId >> 2;          // 0..1  -> 64 rows each
    int warpN = warpId & 3;           // 0..3  -> 32 cols each
    int rowBase = blockIdx.x * BM;
    int colBase = blockIdx.y * BN;

    float acc[4][4][4];
#pragma unroll
    for (int mt = 0; mt < 4; mt++)
#pragma unroll
        for (int nt = 0; nt < 4; nt++)
#pragma unroll
            for (int i = 0; i < 4; i++) acc[mt][nt][i] = 0.0f;

    // A-load indices
    int aRow = tid >> 1;              // 0..127
    int aKoff = (tid & 1) * 16;       // halves
    // B-load indices: coalesced [k][n] copy
    int bK = tid >> 4;                // 0..15
    int bN8 = (tid & 15) * 8;         // n offset, 8 halves per thread

    int gr = rowBase + aRow;
    bool aOk = gr < Nn;
    const __half* aSrc = A + (size_t)gr * K + aKoff;

    for (int k0 = 0; k0 < K; k0 += BK) {
        // ---- A tile (fp16 global -> smem) ----
        uint4 av0 = make_uint4(0, 0, 0, 0), av1 = av0;
        if (aOk) {
            const uint4* ap = (const uint4*)(aSrc + k0);
            av0 = ap[0]; av1 = ap[1];
        }
        *(uint4*)&As[aRow][aKoff] = av0;
        *(uint4*)&As[aRow][aKoff + 8] = av1;
        // ---- B tile: identity coalesced copy, fp16 [k][n] ----
        *(uint4*)&Bs[bK][bN8] =
            *(const uint4*)(Wk + (size_t)(k0 + bK) * Hh + colBase + bN8);
        *(uint4*)&Bs[bK + 16][bN8] =
            *(const uint4*)(Wk + (size_t)(k0 + bK + 16) * Hh + colBase + bN8);
        __syncthreads();

#pragma unroll
        for (int kk = 0; kk < 2; kk++) {
            int kb = kk * 16;
            unsigned afr[4][4];
#pragma unroll
            for (int mt = 0; mt < 4; mt++) {
                int m = warpM * 64 + mt * 16;
                afr[mt][0] = *(const unsigned*)&As[m + g][kb + 2 * q];
                afr[mt][1] = *(const unsigned*)&As[m + g + 8][kb + 2 * q];
                afr[mt][2] = *(const unsigned*)&As[m + g][kb + 2 * q + 8];
                afr[mt][3] = *(const unsigned*)&As[m + g + 8][kb + 2 * q + 8];
            }
#pragma unroll
            for (int nt = 0; nt < 4; nt++) {
                int n0 = warpN * 32 + nt * 8;
                unsigned bfr[2];
                ldsm_x2_trans(bfr[0], bfr[1], &Bs[kb + (lane & 15)][n0]);
#pragma unroll
                for (int mt = 0; mt < 4; mt++)
                    mma_f16(acc[mt][nt], afr[mt], bfr);
            }
        }
        __syncthreads();
    }

    // ---- epilogue ----
#pragma unroll
    for (int mt = 0; mt < 4; mt++) {
        int r0 = rowBase + warpM * 64 + mt * 16 + g;
        int r1 = r0 + 8;
        bool ok0 = r0 < Nn, ok1 = r1 < Nn;
        float sc0 = (ok0 && scaleFlag) ? g_dinv[r0] : 1.0f;
        float sc1 = (ok1 && scaleFlag) ? g_dinv[r1] : 1.0f;
        int gb0 = (ok0 && poolFlag) ? batch[r0] : 0;
        int gb1 = (ok1 && poolFlag) ? batch[r1] : 0;
#pragma unroll
        for (int nt = 0; nt < 4; nt++) {
            int c = colBase + warpN * 32 + nt * 8 + 2 * q;
            float bs0 = bias[c], bs1 = bias[c + 1];
            float v00 = fmaxf(acc[mt][nt][0] + bs0, 0.0f) * sc0;
            float v01 = fmaxf(acc[mt][nt][1] + bs1, 0.0f) * sc0;
            float v10 = fmaxf(acc[mt][nt][2] + bs0, 0.0f) * sc1;
            float v11 = fmaxf(acc[mt][nt][3] + bs1, 0.0f) * sc1;
            if (poolFlag) {
                if (ok0) {
                    atomicAdd(&g_pool[gb0 * Hh + c], v00);
                    atomicAdd(&g_pool[gb0 * Hh + c + 1], v01);
                }
                if (ok1) {
                    atomicAdd(&g_pool[gb1 * Hh + c], v10);
                    atomicAdd(&g_pool[gb1 * Hh + c + 1], v11);
                }
            } else {
                if (ok0) {
                    __half2 h = __floats2half2_rn(v00, v01);
                    *(__half2*)&C[(size_t)r0 * Hh + c] = h;
                }
                if (ok1) {
                    __half2 h = __floats2half2_rn(v10, v11);
                    *(__half2*)&C[(size_t)r1 * Hh + c] = h;
                }
            }
        }
    }
}

// ---------------- output head -------------------------------------------------
__global__ void out_kernel(const float* __restrict__ Wout,
                           const float* __restrict__ bout,
                           float* __restrict__ out) {
    int g = blockIdx.x;
    int lane = threadIdx.x;                 // 32 threads
    float inv = 1.0f / fmaxf(g_cnts[g], 1.0f);
    float p[8];
#pragma unroll
    for (int v = 0; v < 8; v++) p[v] = g_pool[g * Hh + v * 32 + lane] * inv;
#pragma unroll
    for (int t = 0; t < Tt; t++) {
        float s = 0.0f;
#pragma unroll
        for (int v = 0; v < 8; v++) s += p[v] * Wout[(v * 32 + lane) * Tt + t];
#pragma unroll
        for (int off = 16; off; off >>= 1) s += __shfl_down_sync(0xffffffffu, s, off);
        if (lane == 0) out[g * Tt + t] = s + bout[t];
    }
}

// ---------------- launch -----------------------------------------------------
extern "C" void kernel_launch(void* const* d_in, const int* in_sizes, int n_in,
                              void* d_out, int out_size) {
    const float* x    = (const float*)d_in[0];
    const int*   ei   = (const int*)d_in[1];   // [2, E] int32
    const int*   bat  = (const int*)d_in[2];
    const float* W0 = (const float*)d_in[3];  const float* b0 = (const float*)d_in[4];
    const float* W1 = (const float*)d_in[5];  const float* b1 = (const float*)d_in[6];
    const float* W2 = (const float*)d_in[7];  const float* b2 = (const float*)d_in[8];
    const float* W3 = (const float*)d_in[9];  const float* b3 = (const float*)d_in[10];
    const float* Wout = (const float*)d_in[11]; const float* bout = (const float*)d_in[12];
    float* out = (float*)d_out;

    const int* src = ei;
    const int* dst = ei + Ee;

    // prep
    zero_kernel<<<(Gg * Hh + 255) / 256, 256>>>();
    hist_kernel<<<(Ee / 4 + 255) / 256, 256>>>((const int4*)dst);
    scan1_kernel<<<NBLK, 256>>>();
    scan2_kernel<<<1, 256>>>();
    scan3_kernel<<<NBLK, 256>>>(bat);
    fill_kernel<<<(Ee / 4 + 255) / 256, 256>>>((const int4*)src, (const int4*)dst);
    wconv_all_kernel<<<(WTOT + 255) / 256, 256>>>(W0, W1, W2, W3);
    scale_x_kernel<<<(Nn * (Ff / 8) + 255) / 256, 256>>>((const float4*)x);

    dim3 gemmGrid((Nn + BM - 1) / BM, Hh / BN);
    int aggBlocks = (Nn * 32 + 255) / 256;

    __half* W16;
    cudaGetSymbolAddress((void**)&W16, g_W16);

    // layer 0 (K=128)
    agg_kernel<4><<<aggBlocks, 256>>>();
    gemm_f16_kernel<<<gemmGrid, 256>>>(W16 + W0OFF, b0, Ff, 1, 0, bat);
    // layer 1
    agg_kernel<8><<<aggBlocks, 256>>>();
    gemm_f16_kernel<<<gemmGrid, 256>>>(W16 + W1OFF, b1, Hh, 1, 0, bat);
    // layer 2
    agg_kernel<8><<<aggBlocks, 256>>>();
    gemm_f16_kernel<<<gemmGrid, 256>>>(W16 + W2OFF, b2, Hh, 1, 0, bat);
    // layer 3: no dinv pre-scale; fused mean-pool accumulation
    agg_kernel<8><<<aggBlocks, 256>>>();
    gemm_f16_kernel<<<gemmGrid, 256>>>(W16 + W3OFF, b3, Hh, 0, 1, bat);

    // head
    out_kernel<<<Gg, 32>>>(Wout, bout, out);
}

// round 9
// speedup vs baseline: 1.7446x; 1.0308x over previous
#include <cuda_runtime.h>
#include <cuda_fp16.h>

// Problem constants (fixed by the dataset)
#define Nn 50000
#define Ee 800000
#define Ff 128
#define Hh 256
#define Gg 512
#define Tt 5

#define NBLK 196   // ceil(Nn/256) scan blocks

// W16 offsets (halves), [k][n] layout (row-major, n stride 256)
#define W0OFF 0
#define W1OFF 32768
#define W2OFF 98304
#define W3OFF 163840
#define WTOT  229376

// ---------------- scratch (device globals; no allocations allowed) ----------
__device__ int    g_cnt[Nn];
__device__ int    g_rowptr[Nn + 1];
__device__ int    g_cursor[Nn];
__device__ int    g_col[Ee];
__device__ float  g_dinv[Nn];
__device__ int    g_bsum[NBLK];
__device__ int    g_boff[NBLK];
__device__ __half g_W16[WTOT];               // fp16 weights, [k][n]
__device__ __half g_bufA[(size_t)Nn * Hh];   // ping (features, fp16)
__device__ __half g_bufB[(size_t)Nn * Hh];   // pong (aggregation output, fp16)
__device__ float  g_pool[Gg * Hh];
__device__ float  g_cnts[Gg];

// ---------------- prep kernels ----------------------------------------------
// zero + weight conversion fused (both independent elementwise)
__global__ void zero_wconv_kernel(const float* __restrict__ W0,
                                  const float* __restrict__ W1,
                                  const float* __restrict__ W2,
                                  const float* __restrict__ W3) {
    int i = blockIdx.x * blockDim.x + threadIdx.x;
    if (i < Nn) g_cnt[i] = 0;
    if (i < Gg * Hh) g_pool[i] = 0.0f;
    if (i < Gg) g_cnts[i] = 0.0f;
    if (i < WTOT) {
        const float* p; int off;
        if (i < W1OFF)      { p = W0; off = W0OFF; }
        else if (i < W2OFF) { p = W1; off = W1OFF; }
        else if (i < W3OFF) { p = W2; off = W2OFF; }
        else                { p = W3; off = W3OFF; }
        g_W16[i] = __float2half_rn(p[i - off]);
    }
}

__global__ void hist_kernel(const int4* __restrict__ dst4) {
    int e = blockIdx.x * blockDim.x + threadIdx.x;
    if (e < Ee / 4) {
        int4 d = dst4[e];
        if (d.x >= 0 && d.x < Nn) atomicAdd(&g_cnt[d.x], 1);
        if (d.y >= 0 && d.y < Nn) atomicAdd(&g_cnt[d.y], 1);
        if (d.z >= 0 && d.z < Nn) atomicAdd(&g_cnt[d.z], 1);
        if (d.w >= 0 && d.w < Nn) atomicAdd(&g_cnt[d.w], 1);
    }
}

// hierarchical scan: block sums -> scan sums -> per-block rescan
__global__ void scan1_kernel() {
    __shared__ int wsum[8];
    int tid = threadIdx.x, lane = tid & 31, wid = tid >> 5;
    int i = blockIdx.x * 256 + tid;
    int v = (i < Nn) ? g_cnt[i] : 0;
#pragma unroll
    for (int d = 16; d; d >>= 1) v += __shfl_down_sync(0xffffffffu, v, d);
    if (lane == 0) wsum[wid] = v;
    __syncthreads();
    if (tid == 0) {
        int s = 0;
#pragma unroll
        for (int w = 0; w < 8; w++) s += wsum[w];
        g_bsum[blockIdx.x] = s;
    }
}

__global__ void scan2_kernel() {
    __shared__ int s[256];
    int tid = threadIdx.x;
    int v = (tid < NBLK) ? g_bsum[tid] : 0;
    s[tid] = v;
    __syncthreads();
    for (int d = 1; d < 256; d <<= 1) {
        int t = (tid >= d) ? s[tid - d] : 0;
        __syncthreads();
        s[tid] += t;
        __syncthreads();
    }
    if (tid < NBLK) g_boff[tid] = s[tid] - v;   // exclusive
    if (tid == NBLK - 1) g_rowptr[Nn] = s[tid];
}

// scan3 also: dinv, per-graph counts, cursor zero
__global__ void scan3_kernel(const int* __restrict__ batch) {
    __shared__ int wsum[8];
    int tid = threadIdx.x, lane = tid & 31, wid = tid >> 5;
    int i = blockIdx.x * 256 + tid;
    int orig = (i < Nn) ? g_cnt[i] : 0;
    int v = orig;
#pragma unroll
    for (int d = 1; d < 32; d <<= 1) {
        int t = __shfl_up_sync(0xffffffffu, v, d);
        if (lane >= d) v += t;
    }
    if (lane == 31) wsum[wid] = v;
    __syncthreads();
    if (wid == 0 && lane < 8) {
        int s = wsum[lane];
#pragma unroll
        for (int d = 1; d < 8; d <<= 1) {
            int t = __shfl_up_sync(0x000000ffu, s, d);
            if (lane >= d) s += t;
        }
        wsum[lane] = s;
    }
    __syncthreads();
    int prefix = (wid > 0) ? wsum[wid - 1] : 0;
    if (i < Nn) {
        g_rowptr[i] = g_boff[blockIdx.x] + prefix + v - orig;
        g_cursor[i] = 0;
        g_dinv[i] = rsqrtf((float)(orig + 1));   // +1 self-loop
        int g = batch[i];
        if (g >= 0 && g < Gg) atomicAdd(&g_cnts[g], 1.0f);
    }
}

__global__ void fill_kernel(const int4* __restrict__ src4,
                            const int4* __restrict__ dst4) {
    int e = blockIdx.x * blockDim.x + threadIdx.x;
    if (e < Ee / 4) {
        int4 d = dst4[e];
        int4 s = src4[e];
#pragma unroll
        for (int j = 0; j < 4; j++) {
            int dd = (&d.x)[j], ss = (&s.x)[j];
            if (dd >= 0 && dd < Nn && ss >= 0 && ss < Nn) {
                int pos = g_rowptr[dd] + atomicAdd(&g_cursor[dd], 1);
                g_col[pos] = ss;
            }
        }
    }
}

// bufA(fp16) = x * dinv[row]   (width Ff); each thread handles 8 floats
__global__ void scale_x_kernel(const float4* __restrict__ x) {
    int idx = blockIdx.x * blockDim.x + threadIdx.x;   // over Nn * 16
    if (idx < Nn * (Ff / 8)) {
        int row = idx >> 4;
        float d = g_dinv[row];
        float4 v0 = x[idx * 2], v1 = x[idx * 2 + 1];
        __half2 h[4];
        h[0] = __floats2half2_rn(v0.x * d, v0.y * d);
        h[1] = __floats2half2_rn(v0.z * d, v0.w * d);
        h[2] = __floats2half2_rn(v1.x * d, v1.y * d);
        h[3] = __floats2half2_rn(v1.z * d, v1.w * d);
        ((uint4*)g_bufA)[idx] = *(uint4*)h;
    }
}

// ---------------- aggregation (fp16 in, fp32 accum, fp16 out) ---------------
template <int UC> struct VecT;
template <> struct VecT<2> { using T = uint2; };
template <> struct VecT<4> { using T = uint4; };

template <int VH>
__global__ void agg_kernel() {
    constexpr int UC = VH / 2;
    using V = typename VecT<UC>::T;
    int warp = (blockIdx.x * blockDim.x + threadIdx.x) >> 5;
    int lane = threadIdx.x & 31;
    if (warp >= Nn) return;
    const V* __restrict__ hs = (const V*)g_bufA;   // row = 32 V units
    V* __restrict__ outp = (V*)g_bufB;

    float f[VH];
    {
        V v = hs[(size_t)warp * 32 + lane];        // self-loop term
        const unsigned* u = (const unsigned*)&v;
#pragma unroll
        for (int h = 0; h < UC; h++) {
            float2 p = __half22float2(*(const __half2*)&u[h]);
            f[2 * h] = p.x; f[2 * h + 1] = p.y;
        }
    }

    int beg = g_rowptr[warp], end = g_rowptr[warp + 1];
    int e = beg;
    for (; e + 1 < end; e += 2) {
        int s0 = g_col[e], s1 = g_col[e + 1];
        V v0 = hs[(size_t)s0 * 32 + lane];
        V v1 = hs[(size_t)s1 * 32 + lane];
        const unsigned* u0 = (const unsigned*)&v0;
        const unsigned* u1 = (const unsigned*)&v1;
#pragma unroll
        for (int h = 0; h < UC; h++) {
            float2 p0 = __half22float2(*(const __half2*)&u0[h]);
            float2 p1 = __half22float2(*(const __half2*)&u1[h]);
            f[2 * h] += p0.x + p1.x;
            f[2 * h + 1] += p0.y + p1.y;
        }
    }
    if (e < end) {
        int s0 = g_col[e];
        V v0 = hs[(size_t)s0 * 32 + lane];
        const unsigned* u0 = (const unsigned*)&v0;
#pragma unroll
        for (int h = 0; h < UC; h++) {
            float2 p0 = __half22float2(*(const __half2*)&u0[h]);
            f[2 * h] += p0.x;
            f[2 * h + 1] += p0.y;
        }
    }
    float di = g_dinv[warp];
    V ov;
    unsigned* ou = (unsigned*)&ov;
#pragma unroll
    for (int h = 0; h < UC; h++) {
        __half2 p = __floats2half2_rn(f[2 * h] * di, f[2 * h + 1] * di);
        ou[h] = *(unsigned*)&p;
    }
    outp[(size_t)warp * 32 + lane] = ov;
}

// ---------------- fp16 tensor-core GEMM (k-major B + ldmatrix + reg prefetch) -
#define BM 128
#define BN 128
#define BK 32
#define ASTR 40    // A smem row stride (halves)
#define BNP 136    // B smem row stride (halves)

__device__ __forceinline__ void mma_f16(float* c, const unsigned* a, const unsigned* b) {
    asm volatile(
        "mma.sync.aligned.m16n8k16.row.col.f32.f16.f16.f32 "
        "{%0,%1,%2,%3}, {%4,%5,%6,%7}, {%8,%9}, {%0,%1,%2,%3};"
        : "+f"(c[0]), "+f"(c[1]), "+f"(c[2]), "+f"(c[3])
        : "r"(a[0]), "r"(a[1]), "r"(a[2]), "r"(a[3]), "r"(b[0]), "r"(b[1]));
}

__device__ __forceinline__ void ldsm_x2_trans(unsigned& r0, unsigned& r1, const void* p) {
    unsigned addr = (unsigned)__cvta_generic_to_shared(p);
    asm volatile("ldmatrix.sync.aligned.m8n8.x2.trans.shared.b16 {%0,%1}, [%2];"
                 : "=r"(r0), "=r"(r1) : "r"(addr));
}

__global__ __launch_bounds__(256)
void gemm_f16_kernel(const __half* __restrict__ Wk,   // [K][256] fp16
                     const float* __restrict__ bias,
                     int K, int scaleFlag, int poolFlag,
                     const int* __restrict__ batch) {
    __shared__ alignas(16) __half As[BM][ASTR];   // [m][k]
    __shared__ alignas(16) __half Bs[BK][BNP];    // [k][n]

    const __half* __restrict__ A = g_bufB;
    __half* __restrict__ C = g_bufA;

    int tid = threadIdx.x;
    int warpId = tid >> 5, lane = tid & 31;
    int g = lane >> 2, q = lane & 3;
    int warpM = warpId >> 2;          // 0..1  -> 64 rows each
    int warpN = warpId & 3;           // 0..3  -> 32 cols each
    int rowBase = blockIdx.x * BM;
    int colBase = blockIdx.y * BN;

    float acc[4][4][4];
#pragma unroll
    for (int mt = 0; mt < 4; mt++)
#pragma unroll
        for (int nt = 0; nt < 4; nt++)
#pragma unroll
            for (int i = 0; i < 4; i++) acc[mt][nt][i] = 0.0f;

    // A-load indices
    int aRow = tid >> 1;              // 0..127
    int aKoff = (tid & 1) * 16;       // halves
    // B-load indices: coalesced [k][n] copy
    int bK = tid >> 4;                // 0..15
    int bN8 = (tid & 15) * 8;         // n offset, 8 halves per thread

    int gr = rowBase + aRow;
    bool aOk = gr < Nn;
    const __half* aSrc = A + (size_t)gr * K + aKoff;
    const __half* bSrc0 = Wk + (size_t)bK * Hh + colBase + bN8;
    const __half* bSrc1 = Wk + (size_t)(bK + 16) * Hh + colBase + bN8;

    int niter = K / BK;

    // prologue: load iter 0 into regs
    uint4 av0 = make_uint4(0, 0, 0, 0), av1 = av0;
    if (aOk) {
        const uint4* ap = (const uint4*)aSrc;
        av0 = ap[0]; av1 = ap[1];
    }
    uint4 bv0 = *(const uint4*)bSrc0;
    uint4 bv1 = *(const uint4*)bSrc1;

    for (int it = 0; it < niter; it++) {
        // regs -> smem
        *(uint4*)&As[aRow][aKoff] = av0;
        *(uint4*)&As[aRow][aKoff + 8] = av1;
        *(uint4*)&Bs[bK][bN8] = bv0;
        *(uint4*)&Bs[bK + 16][bN8] = bv1;
        __syncthreads();

        // prefetch next iter while computing this one
        if (it + 1 < niter) {
            int k0 = (it + 1) * BK;
            if (aOk) {
                const uint4* ap = (const uint4*)(aSrc + k0);
                av0 = ap[0]; av1 = ap[1];
            }
            bv0 = *(const uint4*)(bSrc0 + (size_t)k0 * Hh);
            bv1 = *(const uint4*)(bSrc1 + (size_t)k0 * Hh);
        }

#pragma unroll
        for (int kk = 0; kk < 2; kk++) {
            int kb = kk * 16;
            unsigned afr[4][4];
#pragma unroll
            for (int mt = 0; mt < 4; mt++) {
                int m = warpM * 64 + mt * 16;
                afr[mt][0] = *(const unsigned*)&As[m + g][kb + 2 * q];
                afr[mt][1] = *(const unsigned*)&As[m + g + 8][kb + 2 * q];
                afr[mt][2] = *(const unsigned*)&As[m + g][kb + 2 * q + 8];
                afr[mt][3] = *(const unsigned*)&As[m + g + 8][kb + 2 * q + 8];
            }
#pragma unroll
            for (int nt = 0; nt < 4; nt++) {
                int n0 = warpN * 32 + nt * 8;
                unsigned bfr[2];
                ldsm_x2_trans(bfr[0], bfr[1], &Bs[kb + (lane & 15)][n0]);
#pragma unroll
                for (int mt = 0; mt < 4; mt++)
                    mma_f16(acc[mt][nt], afr[mt], bfr);
            }
        }
        __syncthreads();
    }

    // ---- epilogue ----
#pragma unroll
    for (int mt = 0; mt < 4; mt++) {
        int r0 = rowBase + warpM * 64 + mt * 16 + g;
        int r1 = r0 + 8;
        bool ok0 = r0 < Nn, ok1 = r1 < Nn;
        float sc0 = (ok0 && scaleFlag) ? g_dinv[r0] : 1.0f;
        float sc1 = (ok1 && scaleFlag) ? g_dinv[r1] : 1.0f;
        int gb0 = (ok0 && poolFlag) ? batch[r0] : 0;
        int gb1 = (ok1 && poolFlag) ? batch[r1] : 0;
#pragma unroll
        for (int nt = 0; nt < 4; nt++) {
            int c = colBase + warpN * 32 + nt * 8 + 2 * q;
            float bs0 = bias[c], bs1 = bias[c + 1];
            float v00 = fmaxf(acc[mt][nt][0] + bs0, 0.0f) * sc0;
            float v01 = fmaxf(acc[mt][nt][1] + bs1, 0.0f) * sc0;
            float v10 = fmaxf(acc[mt][nt][2] + bs0, 0.0f) * sc1;
            float v11 = fmaxf(acc[mt][nt][3] + bs1, 0.0f) * sc1;
            if (poolFlag) {
                if (ok0) {
                    atomicAdd(&g_pool[gb0 * Hh + c], v00);
                    atomicAdd(&g_pool[gb0 * Hh + c + 1], v01);
                }
                if (ok1) {
                    atomicAdd(&g_pool[gb1 * Hh + c], v10);
                    atomicAdd(&g_pool[gb1 * Hh + c + 1], v11);
                }
            } else {
                if (ok0) {
                    __half2 h = __floats2half2_rn(v00, v01);
                    *(__half2*)&C[(size_t)r0 * Hh + c] = h;
                }
                if (ok1) {
                    __half2 h = __floats2half2_rn(v10, v11);
                    *(__half2*)&C[(size_t)r1 * Hh + c] = h;
                }
            }
        }
    }
}

// ---------------- output head -------------------------------------------------
__global__ void out_kernel(const float* __restrict__ Wout,
                           const float* __restrict__ bout,
                           float* __restrict__ out) {
    int g = blockIdx.x;
    int lane = threadIdx.x;                 // 32 threads
    float inv = 1.0f / fmaxf(g_cnts[g], 1.0f);
    float p[8];
#pragma unroll
    for (int v = 0; v < 8; v++) p[v] = g_pool[g * Hh + v * 32 + lane] * inv;
#pragma unroll
    for (int t = 0; t < Tt; t++) {
        float s = 0.0f;
#pragma unroll
        for (int v = 0; v < 8; v++) s += p[v] * Wout[(v * 32 + lane) * Tt + t];
#pragma unroll
        for (int off = 16; off; off >>= 1) s += __shfl_down_sync(0xffffffffu, s, off);
        if (lane == 0) out[g * Tt + t] = s + bout[t];
    }
}

// ---------------- launch -----------------------------------------------------
extern "C" void kernel_launch(void* const* d_in, const int* in_sizes, int n_in,
                              void* d_out, int out_size) {
    const float* x    = (const float*)d_in[0];
    const int*   ei   = (const int*)d_in[1];   // [2, E] int32
    const int*   bat  = (const int*)d_in[2];
    const float* W0 = (const float*)d_in[3];  const float* b0 = (const float*)d_in[4];
    const float* W1 = (const float*)d_in[5];  const float* b1 = (const float*)d_in[6];
    const float* W2 = (const float*)d_in[7];  const float* b2 = (const float*)d_in[8];
    const float* W3 = (const float*)d_in[9];  const float* b3 = (const float*)d_in[10];
    const float* Wout = (const float*)d_in[11]; const float* bout = (const float*)d_in[12];
    float* out = (float*)d_out;

    const int* src = ei;
    const int* dst = ei + Ee;

    // prep
    zero_wconv_kernel<<<(WTOT + 255) / 256, 256>>>(W0, W1, W2, W3);
    hist_kernel<<<(Ee / 4 + 255) / 256, 256>>>((const int4*)dst);
    scan1_kernel<<<NBLK, 256>>>();
    scan2_kernel<<<1, 256>>>();
    scan3_kernel<<<NBLK, 256>>>(bat);
    fill_kernel<<<(Ee / 4 + 255) / 256, 256>>>((const int4*)src, (const int4*)dst);
    scale_x_kernel<<<(Nn * (Ff / 8) + 255) / 256, 256>>>((const float4*)x);

    dim3 gemmGrid((Nn + BM - 1) / BM, Hh / BN);
    int aggBlocks = (Nn * 32 + 255) / 256;

    __half* W16;
    cudaGetSymbolAddress((void**)&W16, g_W16);

    // layer 0 (K=128)
    agg_kernel<4><<<aggBlocks, 256>>>();
    gemm_f16_kernel<<<gemmGrid, 256>>>(W16 + W0OFF, b0, Ff, 1, 0, bat);
    // layer 1
    agg_kernel<8><<<aggBlocks, 256>>>();
    gemm_f16_kernel<<<gemmGrid, 256>>>(W16 + W1OFF, b1, Hh, 1, 0, bat);
    // layer 2
    agg_kernel<8><<<aggBlocks, 256>>>();
    gemm_f16_kernel<<<gemmGrid, 256>>>(W16 + W2OFF, b2, Hh, 1, 0, bat);
    // layer 3: no dinv pre-scale; fused mean-pool accumulation
    agg_kernel<8><<<aggBlocks, 256>>>();
    gemm_f16_kernel<<<gemmGrid, 256>>>(W16 + W3OFF, b3, Hh, 0, 1, bat);

    // head
    out_kernel<<<Gg, 32>>>(Wout, bout, out);
}